// round 10
// baseline (speedup 1.0000x reference)
#include <cuda_runtime.h>

#define NTP 1024  // pass threads

// 8 MB state, tables, composed unitaries — all __device__ globals (no allocs).
__device__ float2 g_psi[16 * 65536];
__device__ float2 g_U[240];        // 60 composed 2x2 unitaries
// Factored layer-0 ring-phase tables: phase(i) = lo[i&0x1FF] * hi[(i>>8)&0xFF | (i&1)<<8]
__device__ float2 g_f0lo[512], g_f0hi[512];   // depth 0
__device__ float2 g_f1lo[512], g_f1hi[512];   // depth 1
__device__ float2 g_t1[512];       // layer1 ring phases (2 depths x 256)
__device__ float2 g_t2[32];        // layer2 (2 x 16)
__device__ float2 g_t3[8];         // layer3 (2 x 4)

__device__ __forceinline__ float2 cmul(float2 a, float2 b) {
    return make_float2(fmaf(a.x, b.x, -a.y * b.y), fmaf(a.x, b.y, a.y * b.x));
}
__device__ __forceinline__ float2 cadd(float2 a, float2 b) {
    return make_float2(a.x + b.x, a.y + b.y);
}
__device__ __forceinline__ void mm2(const float2* A, const float2* B, float2* C) {
    C[0] = cadd(cmul(A[0], B[0]), cmul(A[1], B[2]));
    C[1] = cadd(cmul(A[0], B[1]), cmul(A[1], B[3]));
    C[2] = cadd(cmul(A[2], B[0]), cmul(A[3], B[2]));
    C[3] = cadd(cmul(A[2], B[1]), cmul(A[3], B[3]));
}

// Bank-conflict-killing swizzle (involution): XOR low nibble with bits 4-7.
__device__ __forceinline__ int SWZ(int i) { return i ^ ((i >> 4) & 15); }
// Insert a zero bit at position B.
__device__ __forceinline__ int insb(int x, int B) {
    return ((x >> B) << (B + 1)) | (x & ((1 << B) - 1));
}

struct PhOne {
    __device__ __forceinline__ float2 operator()(int) const { return make_float2(1.f, 0.f); }
};

// Layer-0 factored ring phase lookup (full 16-bit amp index i, batch-free).
__device__ __forceinline__ float2 ring0_d0(int i) {
    return cmul(g_f0lo[i & 0x1FF], g_f0hi[((i >> 8) & 0xFF) | ((i & 1) << 8)]);
}
__device__ __forceinline__ float2 ring0_d1(int i) {
    return cmul(g_f1lo[i & 0x1FF], g_f1hi[((i >> 8) & 0xFF) | ((i & 1) << 8)]);
}

// ---------------------------------------------------------------------------
// Prep: tiny now. Grid 8 x 512 threads. Builds factored ring tables (4 x 512),
// small ring tables, 60 composed unitaries, zeroes output.
// Ring term j couples amp bits (15-j) and (15-(j+1 mod 16)); theta = p0[4j+3(+64d)].
// Lo table: terms j=7..14 (amp bits 8..0). Hi table: terms j=0..6 + j=15,
// indexed by ih = ampbits[15..8] | ampbit0<<8.
// ---------------------------------------------------------------------------
__global__ __launch_bounds__(512) void prep_kernel(
    const float* __restrict__ p0, const float* __restrict__ p1,
    const float* __restrict__ p2, const float* __restrict__ p3,
    float* __restrict__ out)
{
    int T = blockIdx.x * 512 + threadIdx.x;

    if (T < 512) {                      // lo tables (amp bits 8..0 = T bits 8..0)
        float ph0 = 0.f, ph1 = 0.f;
        #pragma unroll
        for (int j = 7; j < 15; j++) {
            int x = ((T >> (15 - j)) ^ (T >> (14 - j))) & 1;
            float sg = x ? 0.5f : -0.5f;
            ph0 += sg * p0[4 * j + 3];
            ph1 += sg * p0[4 * j + 67];
        }
        g_f0lo[T] = make_float2(cosf(ph0), sinf(ph0));
        g_f1lo[T] = make_float2(cosf(ph1), sinf(ph1));
    } else if (T < 1024) {              // hi tables: ih bits 7..0 = amp bits 15..8, bit8 = amp bit0
        int ih = T - 512;
        float ph0 = 0.f, ph1 = 0.f;
        #pragma unroll
        for (int j = 0; j < 7; j++) {
            int x = ((ih >> (7 - j)) ^ (ih >> (6 - j))) & 1;
            float sg = x ? 0.5f : -0.5f;
            ph0 += sg * p0[4 * j + 3];
            ph1 += sg * p0[4 * j + 67];
        }
        {   // term j=15: amp bits 0 (ih bit 8) and 15 (ih bit 7)
            int x = ((ih >> 8) ^ (ih >> 7)) & 1;
            float sg = x ? 0.5f : -0.5f;
            ph0 += sg * p0[63];
            ph1 += sg * p0[127];
        }
        g_f0hi[ih] = make_float2(cosf(ph0), sinf(ph0));
        g_f1hi[ih] = make_float2(cosf(ph1), sinf(ph1));
    } else if (T < 1536) {              // layer1 ring (8 wires), 2 depths x 256
        int tt = T - 1024;
        int d = tt >> 8, idx = tt & 255;
        float ph = 0.f;
        #pragma unroll
        for (int j = 0; j < 8; j++) {
            int jn = (j + 1) & 7;
            int x = ((idx >> (7 - j)) ^ (idx >> (7 - jn))) & 1;
            ph += (x ? 0.5f : -0.5f) * p1[4 * j + 3 + 32 * d];
        }
        g_t1[tt] = make_float2(cosf(ph), sinf(ph));
    } else if (T < 1568) {              // layer2 ring (4 wires)
        int tt = T - 1536;
        int d = tt >> 4, idx = tt & 15;
        float ph = 0.f;
        #pragma unroll
        for (int j = 0; j < 4; j++) {
            int jn = (j + 1) & 3;
            int x = ((idx >> (3 - j)) ^ (idx >> (3 - jn))) & 1;
            ph += (x ? 0.5f : -0.5f) * p2[4 * j + 3 + 16 * d];
        }
        g_t2[tt] = make_float2(cosf(ph), sinf(ph));
    } else if (T < 1576) {              // layer3 (2 wires, 2 rzz terms per depth)
        int tt = T - 1568;
        int d = tt >> 2, idx = tt & 3;
        int x = ((idx >> 1) ^ idx) & 1;
        float sg = x ? 0.5f : -0.5f;
        float ph = sg * (p3[3 + 8 * d] + p3[7 + 8 * d]);
        g_t3[tt] = make_float2(cosf(ph), sinf(ph));
    } else if (T >= 1600 && T < 1660) { // compose 60 unitaries U = RX(c)*RZ(b)*RX(a)
        int t = T - 1600;
        const float* pp; int base;
        if (t < 32)      { pp = p0; int d = t >> 4;        int s = t & 15;       base = 4 * s + 64 * d; }
        else if (t < 48) { pp = p1; int d = (t - 32) >> 3; int s = (t - 32) & 7; base = 4 * s + 32 * d; }
        else if (t < 56) { pp = p2; int d = (t - 48) >> 2; int s = (t - 48) & 3; base = 4 * s + 16 * d; }
        else             { pp = p3; int d = (t - 56) >> 1; int s = (t - 56) & 1; base = 4 * s + 8 * d; }
        float a = pp[base] * 0.5f, b = pp[base + 1] * 0.5f, c = pp[base + 2] * 0.5f;
        float ca = cosf(a), sa = sinf(a);
        float cb = cosf(b), sb = sinf(b);
        float cc = cosf(c), sc = sinf(c);
        float2 RXa[4] = { {ca,0.f}, {0.f,-sa}, {0.f,-sa}, {ca,0.f} };
        float2 RZb[4] = { {cb,-sb}, {0.f,0.f}, {0.f,0.f}, {cb,sb} };
        float2 RXc[4] = { {cc,0.f}, {0.f,-sc}, {0.f,-sc}, {cc,0.f} };
        float2 M[4], U[4];
        mm2(RZb, RXa, M);
        mm2(RXc, M, U);
        g_U[t * 4 + 0] = U[0]; g_U[t * 4 + 1] = U[1];
        g_U[t * 4 + 2] = U[2]; g_U[t * 4 + 3] = U[3];
    } else if (T >= 1664 && T < 1680) {
        out[T - 1664] = 0.f;
    }
}

// ---------------------------------------------------------------------------
// 2-gate cell sweep, single iteration (1024 threads, 1024 cells of 4 amps).
// Gate uh on local bit BH, ul on BL (BH > BL). Coeffs read from smem su.
// Phase functor applied at load (logical index).
// ---------------------------------------------------------------------------
template<int BH, int BL, class PHF>
__device__ __forceinline__ void csweep_ph(float2* s, const float2* su,
                                          int uh, int ul, PHF ph) {
    int c = threadIdx.x;
    int base = insb(insb(c, BL), BH);
    int i01 = base | (1 << BL);
    int i10 = base | (1 << BH);
    int i11 = i10 | (1 << BL);
    float2 a00 = cmul(s[SWZ(base)], ph(base));
    float2 a01 = cmul(s[SWZ(i01)],  ph(i01));
    float2 a10 = cmul(s[SWZ(i10)],  ph(i10));
    float2 a11 = cmul(s[SWZ(i11)],  ph(i11));
    const float2 L0 = su[4*ul], L1 = su[4*ul+1], L2 = su[4*ul+2], L3 = su[4*ul+3];
    float2 b00 = cadd(cmul(L0, a00), cmul(L1, a01));
    float2 b10 = cadd(cmul(L0, a10), cmul(L1, a11));
    float2 b01 = cadd(cmul(L2, a00), cmul(L3, a01));
    float2 b11 = cadd(cmul(L2, a10), cmul(L3, a11));
    const float2 H0 = su[4*uh], H1 = su[4*uh+1], H2 = su[4*uh+2], H3 = su[4*uh+3];
    s[SWZ(base)] = cadd(cmul(H0, b00), cmul(H1, b10));
    s[SWZ(i10)]  = cadd(cmul(H2, b00), cmul(H3, b10));
    s[SWZ(i01)]  = cadd(cmul(H0, b01), cmul(H1, b11));
    s[SWZ(i11)]  = cadd(cmul(H2, b01), cmul(H3, b11));
    __syncthreads();
}
template<int BH, int BL>
__device__ __forceinline__ void csweep(float2* s, const float2* su, int uh, int ul) {
    csweep_ph<BH, BL>(s, su, uh, ul, PhOne());
}

// ---------------------------------------------------------------------------
// Fused diagonal + CNOT-layer permutation (XOR involution). new[l]=old[p]*ph(p).
// ---------------------------------------------------------------------------
template<class FXF, class PHF>
__device__ __forceinline__ void perm_ph(float2* s, FXF fx, PHF ph) {
    #pragma unroll
    for (int i = 0; i < 4; i++) {
        int l = threadIdx.x + i * NTP;
        int f = fx(l);
        int p = l ^ f;
        if (f == 0) {
            s[SWZ(l)] = cmul(s[SWZ(l)], ph(l));
        } else if (l < p) {
            float2 a = s[SWZ(l)], b = s[SWZ(p)];
            s[SWZ(l)] = cmul(b, ph(p));
            s[SWZ(p)] = cmul(a, ph(l));
        }
    }
    __syncthreads();
}

// ---------------------------------------------------------------------------
// Pass 1: local = amp bits 0..11 (wires 4..15). Layer0 d0 on wires 4..15.
// Local bit b holds wire 15-b -> U(15-b).
// ---------------------------------------------------------------------------
__global__ __launch_bounds__(NTP, 2) void pass1_kernel(
    const float* __restrict__ xre, const float* __restrict__ xim)
{
    __shared__ float2 s[4096];
    __shared__ float2 su[240];
    int tid = threadIdx.x;
    if (tid < 240) su[tid] = g_U[tid];
    int b = blockIdx.x >> 4, tile = blockIdx.x & 15;
    int base = (b << 16) | (tile << 12);
    #pragma unroll
    for (int i = 0; i < 4; i++) {
        int l = tid + i * NTP;
        s[SWZ(l)] = make_float2(xre[base + l], xim[base + l]);
    }
    __syncthreads();
    csweep<11, 0>(s, su, 4, 15);
    csweep<10, 1>(s, su, 5, 14);
    csweep<9, 2>(s, su, 6, 13);
    csweep<8, 3>(s, su, 7, 12);
    csweep<7, 4>(s, su, 8, 11);
    csweep<6, 5>(s, su, 9, 10);
    #pragma unroll
    for (int i = 0; i < 4; i++) {
        int l = tid + i * NTP;
        g_psi[base + l] = s[SWZ(l)];
    }
}

// ---------------------------------------------------------------------------
// Pass 2: local amp bits {0-4,7,9,11,12-15}. d0 on wires 0-3; diag D0; d1 on
// 12 local wires. Global amp bits {5,6,8,10}.
// ---------------------------------------------------------------------------
__device__ __forceinline__ int expand2x(int l) {
    return (l & 0x1F) | ((l & 0x20) << 2) | ((l & 0x40) << 3) | ((l & 0xF80) << 4);
}
__global__ __launch_bounds__(NTP, 2) void pass2_kernel() {
    __shared__ float2 s[4096];
    __shared__ float2 su[240];
    int tid = threadIdx.x;
    if (tid < 240) su[tid] = g_U[tid];
    int b = blockIdx.x >> 4, tile = blockIdx.x & 15;
    unsigned tor = ((tile & 3) << 5) | ((tile & 4) << 6) | ((tile & 8) << 7);
    unsigned gb = (unsigned)b << 16;
    #pragma unroll
    for (int i = 0; i < 4; i++) {
        int l = tid + i * NTP;
        s[SWZ(l)] = g_psi[gb | tor | expand2x(l)];
    }
    __syncthreads();
    // layer0 d0 on wires 0..3 (locals 11,10,9,8)
    csweep<11, 8>(s, su, 0, 3);
    csweep<10, 9>(s, su, 1, 2);
    // layer0 d1, ring diag D0 folded into the first sweep's load
    csweep_ph<11, 0>(s, su, 16, 31, [&](int l) { return ring0_d0(tor | expand2x(l)); });
    csweep<10, 1>(s, su, 17, 30);
    csweep<9, 2>(s, su, 18, 29);
    csweep<8, 3>(s, su, 19, 28);
    csweep<7, 4>(s, su, 20, 27);
    csweep<6, 5>(s, su, 22, 24);
    #pragma unroll
    for (int i = 0; i < 4; i++) {
        int l = tid + i * NTP;
        g_psi[gb | tor | expand2x(l)] = s[SWZ(l)];
    }
}

// ---------------------------------------------------------------------------
// Pass 3: local amp bits {0-6,8,10,12,14,15}. Global amp bits {7,9,11,13}.
// Local map: l11=w0 l10=w1 l9=w3 l8=w5 l7=w7 l6=w9 l5=w10 l4..l0=w11..w15.
// ---------------------------------------------------------------------------
__device__ __forceinline__ int expand3x(int l) {
    return (l & 0x7F) | ((l & 0x80) << 1) | ((l & 0x100) << 2) |
           ((l & 0x200) << 3) | ((l & 0xC00) << 4);
}
__global__ __launch_bounds__(NTP, 2) void pass3_kernel() {
    __shared__ float2 s[4096];
    __shared__ float2 su[240];
    int tid = threadIdx.x;
    if (tid < 240) su[tid] = g_U[tid];
    int b = blockIdx.x >> 4, tile = blockIdx.x & 15;
    unsigned tor = ((tile & 1) << 7) | ((tile & 2) << 8) | ((tile & 4) << 9) | ((tile & 8) << 10);
    unsigned gb = (unsigned)b << 16;
    #pragma unroll
    for (int i = 0; i < 4; i++) {
        int l = tid + i * NTP;
        s[SWZ(l)] = g_psi[gb | tor | expand3x(l)];
    }
    __syncthreads();
    // layer0 d1 leftovers: w5->l8(U21), w7->l7(U23), w9->l6(U25), w10->l5(U26)
    csweep<8, 5>(s, su, 21, 26);
    csweep<7, 6>(s, su, 23, 25);
    // diag D1 + all 8 pool CNOTs fused (targets l10,l9,l8,l7,l6,l4,l2,l0).
    {
        int fc = (((tile >> 3) & 1) << 9) | (((tile >> 2) & 1) << 8) |
                 (((tile >> 1) & 1) << 7) | ((tile & 1) << 6);
        perm_ph(s,
            [&](int l) {
                return ((((l >> 11) & 1) << 10) | (((l >> 5) & 1) << 4) |
                        (((l >> 3) & 1) << 2) | ((l >> 1) & 1)) | fc;
            },
            [&](int l) { return ring0_d1(tor | expand3x(l)); });
    }
    // layer1 d0 on wires 0,10,12,14 -> locals 11(U32),5(U37),3(U38),1(U39)
    csweep<11, 1>(s, su, 32, 39);
    csweep<5, 3>(s, su, 37, 38);
    #pragma unroll
    for (int i = 0; i < 4; i++) {
        int l = tid + i * NTP;
        g_psi[gb | tor | expand3x(l)] = s[SWZ(l)];
    }
}

// ---------------------------------------------------------------------------
// Pass 4: local amp bits {0-7,9,11,13,15}. Global amp bits {8,10,12,14}.
// Local map: l11=w0 l10=w2 l9=w4 l8=w6 l7=w8 l5=w10 l3=w12 l1=w14.
// ---------------------------------------------------------------------------
__device__ __forceinline__ int expand4x(int l) {
    return (l & 0xFF) | ((l & 0x100) << 1) | ((l & 0x200) << 2) |
           ((l & 0x400) << 3) | ((l & 0x800) << 4);
}
__device__ __forceinline__ int p4_idx8(int l) {
    return ((l >> 4) & 0xF8) | ((l >> 3) & 4) | ((l >> 2) & 2) | ((l >> 1) & 1);
}
__device__ __forceinline__ int p4_idx4(int l) {
    return ((l >> 8) & 8) | ((l >> 7) & 4) | ((l >> 6) & 2) | ((l >> 3) & 1);
}
__device__ __forceinline__ int p4_idx2(int l) {
    return ((l >> 10) & 2) | ((l >> 7) & 1);
}
__global__ __launch_bounds__(NTP, 2) void pass4_kernel(float* __restrict__ out) {
    __shared__ float2 s[4096];
    __shared__ float2 su[240];
    __shared__ float ws[32];
    int tid = threadIdx.x;
    if (tid < 240) su[tid] = g_U[tid];
    int b = blockIdx.x >> 4, tile = blockIdx.x & 15;
    unsigned tor = ((tile & 1) << 8) | ((tile & 2) << 9) | ((tile & 4) << 10) | ((tile & 8) << 11);
    unsigned gb = (unsigned)b << 16;
    #pragma unroll
    for (int i = 0; i < 4; i++) {
        int l = tid + i * NTP;
        s[SWZ(l)] = g_psi[gb | tor | expand4x(l)];
    }
    __syncthreads();

    // layer1 d0 leftovers: w2->l10(U33), w4->l9(U34), w6->l8(U35), w8->l7(U36)
    csweep<10, 7>(s, su, 33, 36);
    csweep<9, 8>(s, su, 34, 35);
    // layer1 d1 (8 gates) with diag D0 folded into the first sweep
    csweep_ph<11, 1>(s, su, 40, 47, [&](int l) { return g_t1[p4_idx8(l)]; });
    csweep<10, 3>(s, su, 41, 46);
    csweep<9, 5>(s, su, 42, 45);
    csweep<8, 7>(s, su, 43, 44);
    // diag D1 + layer1 pool (l10<-l11, l8<-l9, l5<-l7, l1<-l3)
    perm_ph(s,
        [&](int l) {
            return (((l >> 11) & 1) << 10) | (((l >> 9) & 1) << 8) |
                   (((l >> 7) & 1) << 5) | (((l >> 3) & 1) << 1);
        },
        [&](int l) { return g_t1[256 + p4_idx8(l)]; });

    // layer2 d0: w0->l11(U48), w4->l9(U49), w8->l7(U50), w12->l3(U51)
    csweep<11, 3>(s, su, 48, 51);
    csweep<9, 7>(s, su, 49, 50);
    // layer2 d1 with diag D0 folded
    csweep_ph<11, 3>(s, su, 52, 55, [&](int l) { return g_t2[p4_idx4(l)]; });
    csweep<9, 7>(s, su, 53, 54);
    // diag D1 + layer2 pool (l9<-l11, l3<-l7)
    perm_ph(s,
        [&](int l) {
            return (((l >> 11) & 1) << 9) | (((l >> 7) & 1) << 3);
        },
        [&](int l) { return g_t2[16 + p4_idx4(l)]; });

    // layer3 d0: w0->l11(U56), w8->l7(U57)
    csweep<11, 7>(s, su, 56, 57);
    // layer3 d1 with diag D0 folded
    csweep_ph<11, 7>(s, su, 58, 59, [&](int l) { return g_t3[p4_idx2(l)]; });
    // diag D1 + layer3 pool (l7<-l11)
    perm_ph(s,
        [&](int l) { return ((l >> 11) & 1) << 7; },
        [&](int l) { return g_t3[4 + p4_idx2(l)]; });

    // measure Z on wire 0 (local bit 11)
    float acc = 0.f;
    #pragma unroll
    for (int i = 0; i < 4; i++) {
        int l = tid + i * NTP;
        float2 a = s[SWZ(l)];
        float p = fmaf(a.x, a.x, a.y * a.y);
        acc += ((l >> 11) & 1) ? -p : p;
    }
    #pragma unroll
    for (int o = 16; o > 0; o >>= 1) acc += __shfl_xor_sync(0xFFFFFFFFu, acc, o);
    if ((tid & 31) == 0) ws[tid >> 5] = acc;
    __syncthreads();
    if (tid == 0) {
        float t = 0.f;
        #pragma unroll
        for (int k = 0; k < 32; k++) t += ws[k];
        atomicAdd(&out[b], t);
    }
}

// ---------------------------------------------------------------------------
extern "C" void kernel_launch(void* const* d_in, const int* in_sizes, int n_in,
                              void* d_out, int out_size) {
    const float* xre = (const float*)d_in[0];
    const float* xim = (const float*)d_in[1];
    const float* p0  = (const float*)d_in[2];
    const float* p1  = (const float*)d_in[3];
    const float* p2  = (const float*)d_in[4];
    const float* p3  = (const float*)d_in[5];
    float* out = (float*)d_out;

    prep_kernel<<<8, 512>>>(p0, p1, p2, p3, out);
    pass1_kernel<<<256, NTP>>>(xre, xim);
    pass2_kernel<<<256, NTP>>>();
    pass3_kernel<<<256, NTP>>>();
    pass4_kernel<<<256, NTP>>>(out);
}

// round 11
// speedup vs baseline: 1.1734x; 1.1734x over previous
#include <cuda_runtime.h>

#define NTP 512   // pass threads

// 8 MB state, tables, composed unitaries — all __device__ globals (no allocs).
__device__ float2 g_psi[16 * 65536];
__device__ float2 g_U[240];        // 60 composed 2x2 unitaries
// Factored layer-0 ring-phase tables: phase(i) = lo[i&0x1FF] * hi[(i>>8)&0xFF | (i&1)<<8]
__device__ float2 g_f0lo[512], g_f0hi[512];   // depth 0
__device__ float2 g_f1lo[512], g_f1hi[512];   // depth 1
__device__ float2 g_t1[512];       // layer1 ring phases (2 depths x 256)
__device__ float2 g_t2[32];        // layer2 (2 x 16)
__device__ float2 g_t3[8];         // layer3 (2 x 4)

__device__ __forceinline__ float2 cmul(float2 a, float2 b) {
    return make_float2(fmaf(a.x, b.x, -a.y * b.y), fmaf(a.x, b.y, a.y * b.x));
}
__device__ __forceinline__ float2 cadd(float2 a, float2 b) {
    return make_float2(a.x + b.x, a.y + b.y);
}
__device__ __forceinline__ void mm2(const float2* A, const float2* B, float2* C) {
    C[0] = cadd(cmul(A[0], B[0]), cmul(A[1], B[2]));
    C[1] = cadd(cmul(A[0], B[1]), cmul(A[1], B[3]));
    C[2] = cadd(cmul(A[2], B[0]), cmul(A[3], B[2]));
    C[3] = cadd(cmul(A[2], B[1]), cmul(A[3], B[3]));
}

// Bank-conflict-killing swizzle (involution): XOR low nibble with bits 4-7.
__device__ __forceinline__ int SWZ(int i) { return i ^ ((i >> 4) & 15); }
// Insert a zero bit at position B.
__device__ __forceinline__ int insb(int x, int B) {
    return ((x >> B) << (B + 1)) | (x & ((1 << B) - 1));
}

struct PhOne {
    __device__ __forceinline__ float2 operator()(int) const { return make_float2(1.f, 0.f); }
};

// Layer-0 factored ring phase lookup (full 16-bit amp index, batch-free).
__device__ __forceinline__ float2 ring0_d0(int i) {
    return cmul(g_f0lo[i & 0x1FF], g_f0hi[((i >> 8) & 0xFF) | ((i & 1) << 8)]);
}
__device__ __forceinline__ float2 ring0_d1(int i) {
    return cmul(g_f1lo[i & 0x1FF], g_f1hi[((i >> 8) & 0xFF) | ((i & 1) << 8)]);
}

// ---------------------------------------------------------------------------
// Prep (tiny): factored ring tables, small ring tables, 60 composed unitaries.
// Ring term j couples amp bits (15-j) and (15-(j+1 mod 16)).
// Lo: terms j=7..14 (amp bits 8..0). Hi: terms j=0..6 + j=15,
// ih = ampbits[15..8] | ampbit0<<8.
// ---------------------------------------------------------------------------
__global__ __launch_bounds__(512) void prep_kernel(
    const float* __restrict__ p0, const float* __restrict__ p1,
    const float* __restrict__ p2, const float* __restrict__ p3,
    float* __restrict__ out)
{
    int T = blockIdx.x * 512 + threadIdx.x;

    if (T < 512) {                      // lo tables (amp bits 8..0)
        float ph0 = 0.f, ph1 = 0.f;
        #pragma unroll
        for (int j = 7; j < 15; j++) {
            int x = ((T >> (15 - j)) ^ (T >> (14 - j))) & 1;
            float sg = x ? 0.5f : -0.5f;
            ph0 += sg * p0[4 * j + 3];
            ph1 += sg * p0[4 * j + 67];
        }
        g_f0lo[T] = make_float2(cosf(ph0), sinf(ph0));
        g_f1lo[T] = make_float2(cosf(ph1), sinf(ph1));
    } else if (T < 1024) {              // hi tables
        int ih = T - 512;
        float ph0 = 0.f, ph1 = 0.f;
        #pragma unroll
        for (int j = 0; j < 7; j++) {
            int x = ((ih >> (7 - j)) ^ (ih >> (6 - j))) & 1;
            float sg = x ? 0.5f : -0.5f;
            ph0 += sg * p0[4 * j + 3];
            ph1 += sg * p0[4 * j + 67];
        }
        {   // term j=15: amp bits 0 (ih bit 8) and 15 (ih bit 7)
            int x = ((ih >> 8) ^ (ih >> 7)) & 1;
            float sg = x ? 0.5f : -0.5f;
            ph0 += sg * p0[63];
            ph1 += sg * p0[127];
        }
        g_f0hi[ih] = make_float2(cosf(ph0), sinf(ph0));
        g_f1hi[ih] = make_float2(cosf(ph1), sinf(ph1));
    } else if (T < 1536) {              // layer1 ring (8 wires), 2 depths x 256
        int tt = T - 1024;
        int d = tt >> 8, idx = tt & 255;
        float ph = 0.f;
        #pragma unroll
        for (int j = 0; j < 8; j++) {
            int jn = (j + 1) & 7;
            int x = ((idx >> (7 - j)) ^ (idx >> (7 - jn))) & 1;
            ph += (x ? 0.5f : -0.5f) * p1[4 * j + 3 + 32 * d];
        }
        g_t1[tt] = make_float2(cosf(ph), sinf(ph));
    } else if (T < 1568) {              // layer2 ring (4 wires)
        int tt = T - 1536;
        int d = tt >> 4, idx = tt & 15;
        float ph = 0.f;
        #pragma unroll
        for (int j = 0; j < 4; j++) {
            int jn = (j + 1) & 3;
            int x = ((idx >> (3 - j)) ^ (idx >> (3 - jn))) & 1;
            ph += (x ? 0.5f : -0.5f) * p2[4 * j + 3 + 16 * d];
        }
        g_t2[tt] = make_float2(cosf(ph), sinf(ph));
    } else if (T < 1576) {              // layer3 (2 wires)
        int tt = T - 1568;
        int d = tt >> 2, idx = tt & 3;
        int x = ((idx >> 1) ^ idx) & 1;
        float sg = x ? 0.5f : -0.5f;
        float ph = sg * (p3[3 + 8 * d] + p3[7 + 8 * d]);
        g_t3[tt] = make_float2(cosf(ph), sinf(ph));
    } else if (T >= 1600 && T < 1660) { // compose 60 unitaries U = RX(c)*RZ(b)*RX(a)
        int t = T - 1600;
        const float* pp; int base;
        if (t < 32)      { pp = p0; int d = t >> 4;        int s = t & 15;       base = 4 * s + 64 * d; }
        else if (t < 48) { pp = p1; int d = (t - 32) >> 3; int s = (t - 32) & 7; base = 4 * s + 32 * d; }
        else if (t < 56) { pp = p2; int d = (t - 48) >> 2; int s = (t - 48) & 3; base = 4 * s + 16 * d; }
        else             { pp = p3; int d = (t - 56) >> 1; int s = (t - 56) & 1; base = 4 * s + 8 * d; }
        float a = pp[base] * 0.5f, b = pp[base + 1] * 0.5f, c = pp[base + 2] * 0.5f;
        float ca = cosf(a), sa = sinf(a);
        float cb = cosf(b), sb = sinf(b);
        float cc = cosf(c), sc = sinf(c);
        float2 RXa[4] = { {ca,0.f}, {0.f,-sa}, {0.f,-sa}, {ca,0.f} };
        float2 RZb[4] = { {cb,-sb}, {0.f,0.f}, {0.f,0.f}, {cb,sb} };
        float2 RXc[4] = { {cc,0.f}, {0.f,-sc}, {0.f,-sc}, {cc,0.f} };
        float2 M[4], U[4];
        mm2(RZb, RXa, M);
        mm2(RXc, M, U);
        g_U[t * 4 + 0] = U[0]; g_U[t * 4 + 1] = U[1];
        g_U[t * 4 + 2] = U[2]; g_U[t * 4 + 3] = U[3];
    } else if (T >= 1664 && T < 1680) {
        out[T - 1664] = 0.f;
    }
}

// ---------------------------------------------------------------------------
// 2-gate cell kernel core: gates uh on bit BH, ul on bit BL (BH > BL).
// 1024 cells of 4 amps, 512 threads x 2 iterations.
// ---------------------------------------------------------------------------
#define CSWEEP_CORE(LOAD, STORE)                                              \
    const float2 H0 = g_U[4*uh], H1 = g_U[4*uh+1],                            \
                 H2 = g_U[4*uh+2], H3 = g_U[4*uh+3];                          \
    const float2 L0 = g_U[4*ul], L1 = g_U[4*ul+1],                            \
                 L2 = g_U[4*ul+2], L3 = g_U[4*ul+3];                          \
    _Pragma("unroll")                                                         \
    for (int it = 0; it < 2; it++) {                                          \
        int c = threadIdx.x + it * NTP;                                       \
        int base = insb(insb(c, BL), BH);                                     \
        int i01 = base | (1 << BL);                                           \
        int i10 = base | (1 << BH);                                           \
        int i11 = i10 | (1 << BL);                                            \
        float2 a00 = LOAD(base), a01 = LOAD(i01);                             \
        float2 a10 = LOAD(i10),  a11 = LOAD(i11);                             \
        float2 b00 = cadd(cmul(L0, a00), cmul(L1, a01));                      \
        float2 b10 = cadd(cmul(L0, a10), cmul(L1, a11));                      \
        float2 b01 = cadd(cmul(L2, a00), cmul(L3, a01));                      \
        float2 b11 = cadd(cmul(L2, a10), cmul(L3, a11));                      \
        float2 r00 = cadd(cmul(H0, b00), cmul(H1, b10));                      \
        float2 r10 = cadd(cmul(H2, b00), cmul(H3, b10));                      \
        float2 r01 = cadd(cmul(H0, b01), cmul(H1, b11));                      \
        float2 r11 = cadd(cmul(H2, b01), cmul(H3, b11));                      \
        STORE;                                                                \
    }

// smem -> smem, with optional load phase
template<int BH, int BL, class PHF>
__device__ __forceinline__ void csweep_ph(float2* s, int uh, int ul, PHF ph) {
    #define LD_(i) cmul(s[SWZ(i)], ph(i))
    #define ST_ { s[SWZ(base)] = r00; s[SWZ(i01)] = r01; \
                  s[SWZ(i10)] = r10;  s[SWZ(i11)] = r11; }
    CSWEEP_CORE(LD_, ST_)
    #undef LD_
    #undef ST_
    __syncthreads();
}
template<int BH, int BL>
__device__ __forceinline__ void csweep(float2* s, int uh, int ul) {
    csweep_ph<BH, BL>(s, uh, ul, PhOne());
}

// global -> smem (fused tile-load + first sweep)
template<int BH, int BL, class LDF>
__device__ __forceinline__ void csweep_ld(float2* s, int uh, int ul, LDF gld) {
    #define LD_(i) gld(i)
    #define ST_ { s[SWZ(base)] = r00; s[SWZ(i01)] = r01; \
                  s[SWZ(i10)] = r10;  s[SWZ(i11)] = r11; }
    CSWEEP_CORE(LD_, ST_)
    #undef LD_
    #undef ST_
    __syncthreads();
}

// smem -> global (fused last sweep + tile-store); no trailing barrier needed
template<int BH, int BL, class STF>
__device__ __forceinline__ void csweep_st(float2* s, int uh, int ul, STF gst) {
    #define LD_(i) s[SWZ(i)]
    #define ST_ { gst(base, r00); gst(i01, r01); gst(i10, r10); gst(i11, r11); }
    CSWEEP_CORE(LD_, ST_)
    #undef LD_
    #undef ST_
}

// smem -> Z-measurement on bit BH (fused last sweep + measure; no stores)
template<int BH, int BL, class PHF>
__device__ __forceinline__ float csweep_meas(float2* s, int uh, int ul, PHF ph) {
    float acc = 0.f;
    #define LD_(i) cmul(s[SWZ(i)], ph(i))
    #define ST_ { acc += fmaf(r00.x, r00.x, r00.y * r00.y);                   \
                  acc += fmaf(r01.x, r01.x, r01.y * r01.y);                   \
                  acc -= fmaf(r10.x, r10.x, r10.y * r10.y);                   \
                  acc -= fmaf(r11.x, r11.x, r11.y * r11.y); }
    CSWEEP_CORE(LD_, ST_)
    #undef LD_
    #undef ST_
    return acc;
}

// ---------------------------------------------------------------------------
// Fused diagonal + CNOT-layer permutation (XOR involution). new[l]=old[p]*ph(p).
// ---------------------------------------------------------------------------
template<class FXF, class PHF>
__device__ __forceinline__ void perm_ph(float2* s, FXF fx, PHF ph) {
    #pragma unroll
    for (int i = 0; i < 8; i++) {
        int l = threadIdx.x + i * NTP;
        int f = fx(l);
        int p = l ^ f;
        if (f == 0) {
            s[SWZ(l)] = cmul(s[SWZ(l)], ph(l));
        } else if (l < p) {
            float2 a = s[SWZ(l)], b = s[SWZ(p)];
            s[SWZ(l)] = cmul(b, ph(p));
            s[SWZ(p)] = cmul(a, ph(l));
        }
    }
    __syncthreads();
}

// ---------------------------------------------------------------------------
// Pass 1: local = amp bits 0..11 (wires 4..15). Layer0 d0 on wires 4..15.
// Local bit b holds wire 15-b -> U(15-b).
// ---------------------------------------------------------------------------
__global__ __launch_bounds__(NTP, 2) void pass1_kernel(
    const float* __restrict__ xre, const float* __restrict__ xim)
{
    __shared__ float2 s[4096];
    int b = blockIdx.x >> 4, tile = blockIdx.x & 15;
    int base = (b << 16) | (tile << 12);
    csweep_ld<11, 0>(s, 4, 15,
        [&](int l) { return make_float2(xre[base + l], xim[base + l]); });
    csweep<10, 1>(s, 5, 14);
    csweep<9, 2>(s, 6, 13);
    csweep<8, 3>(s, 7, 12);
    csweep<7, 4>(s, 8, 11);
    csweep_st<6, 5>(s, 9, 10,
        [&](int l, float2 v) { g_psi[base + l] = v; });
}

// ---------------------------------------------------------------------------
// Pass 2: local amp bits {0-4,7,9,11,12-15}. d0 on wires 0-3; ring D0; d1 on
// 12 local wires. Global amp bits {5,6,8,10}.
// ---------------------------------------------------------------------------
__device__ __forceinline__ int expand2x(int l) {
    return (l & 0x1F) | ((l & 0x20) << 2) | ((l & 0x40) << 3) | ((l & 0xF80) << 4);
}
__global__ __launch_bounds__(NTP, 2) void pass2_kernel() {
    __shared__ float2 s[4096];
    int b = blockIdx.x >> 4, tile = blockIdx.x & 15;
    unsigned tor = ((tile & 3) << 5) | ((tile & 4) << 6) | ((tile & 8) << 7);
    unsigned gb = (unsigned)b << 16;
    // layer0 d0 on wires 0..3 (locals 11,10,9,8) — first sweep fused with load
    csweep_ld<11, 8>(s, 0, 3,
        [&](int l) { return g_psi[gb | tor | expand2x(l)]; });
    csweep<10, 9>(s, 1, 2);
    // layer0 d1, ring diag D0 folded into the first sweep's load
    csweep_ph<11, 0>(s, 16, 31, [&](int l) { return ring0_d0(tor | expand2x(l)); });
    csweep<10, 1>(s, 17, 30);
    csweep<9, 2>(s, 18, 29);
    csweep<8, 3>(s, 19, 28);
    csweep<7, 4>(s, 20, 27);
    csweep_st<6, 5>(s, 22, 24,
        [&](int l, float2 v) { g_psi[gb | tor | expand2x(l)] = v; });
}

// ---------------------------------------------------------------------------
// Pass 3: local amp bits {0-6,8,10,12,14,15}. Global amp bits {7,9,11,13}.
// Local map: l11=w0 l10=w1 l9=w3 l8=w5 l7=w7 l6=w9 l5=w10 l4..l0=w11..w15.
// ---------------------------------------------------------------------------
__device__ __forceinline__ int expand3x(int l) {
    return (l & 0x7F) | ((l & 0x80) << 1) | ((l & 0x100) << 2) |
           ((l & 0x200) << 3) | ((l & 0xC00) << 4);
}
__global__ __launch_bounds__(NTP, 2) void pass3_kernel() {
    __shared__ float2 s[4096];
    int b = blockIdx.x >> 4, tile = blockIdx.x & 15;
    unsigned tor = ((tile & 1) << 7) | ((tile & 2) << 8) | ((tile & 4) << 9) | ((tile & 8) << 10);
    unsigned gb = (unsigned)b << 16;
    // layer0 d1 leftovers: w5->l8(U21), w7->l7(U23), w9->l6(U25), w10->l5(U26)
    csweep_ld<8, 5>(s, 21, 26,
        [&](int l) { return g_psi[gb | tor | expand3x(l)]; });
    csweep<7, 6>(s, 23, 25);
    // ring D1 + all 8 pool CNOTs fused (targets l10,l9,l8,l7,l6,l4,l2,l0).
    {
        int fc = (((tile >> 3) & 1) << 9) | (((tile >> 2) & 1) << 8) |
                 (((tile >> 1) & 1) << 7) | ((tile & 1) << 6);
        perm_ph(s,
            [&](int l) {
                return ((((l >> 11) & 1) << 10) | (((l >> 5) & 1) << 4) |
                        (((l >> 3) & 1) << 2) | ((l >> 1) & 1)) | fc;
            },
            [&](int l) { return ring0_d1(tor | expand3x(l)); });
    }
    // layer1 d0 on wires 0,10,12,14 -> locals 11(U32),5(U37),3(U38),1(U39)
    csweep<11, 1>(s, 32, 39);
    csweep_st<5, 3>(s, 37, 38,
        [&](int l, float2 v) { g_psi[gb | tor | expand3x(l)] = v; });
}

// ---------------------------------------------------------------------------
// Pass 4: local amp bits {0-7,9,11,13,15}. Global amp bits {8,10,12,14}.
// Local map: l11=w0 l10=w2 l9=w4 l8=w6 l7=w8 l5=w10 l3=w12 l1=w14.
// Final diagonal (t3 d1) and final pool CNOT (ctrl=bit11, tgt=bit7) cannot
// change <Z(bit11)> — dropped. Measurement fused into the last unitary sweep.
// ---------------------------------------------------------------------------
__device__ __forceinline__ int expand4x(int l) {
    return (l & 0xFF) | ((l & 0x100) << 1) | ((l & 0x200) << 2) |
           ((l & 0x400) << 3) | ((l & 0x800) << 4);
}
__device__ __forceinline__ int p4_idx8(int l) {
    return ((l >> 4) & 0xF8) | ((l >> 3) & 4) | ((l >> 2) & 2) | ((l >> 1) & 1);
}
__device__ __forceinline__ int p4_idx4(int l) {
    return ((l >> 8) & 8) | ((l >> 7) & 4) | ((l >> 6) & 2) | ((l >> 3) & 1);
}
__device__ __forceinline__ int p4_idx2(int l) {
    return ((l >> 10) & 2) | ((l >> 7) & 1);
}
__global__ __launch_bounds__(NTP, 2) void pass4_kernel(float* __restrict__ out) {
    __shared__ float2 s[4096];
    __shared__ float ws[16];
    int tid = threadIdx.x;
    int b = blockIdx.x >> 4, tile = blockIdx.x & 15;
    unsigned tor = ((tile & 1) << 8) | ((tile & 2) << 9) | ((tile & 4) << 10) | ((tile & 8) << 11);
    unsigned gb = (unsigned)b << 16;

    // layer1 d0 leftovers: w2->l10(U33), w4->l9(U34), w6->l8(U35), w8->l7(U36)
    csweep_ld<10, 7>(s, 33, 36,
        [&](int l) { return g_psi[gb | tor | expand4x(l)]; });
    csweep<9, 8>(s, 34, 35);
    // layer1 d1 (8 gates) with ring d0 folded into the first sweep
    csweep_ph<11, 1>(s, 40, 47, [&](int l) { return g_t1[p4_idx8(l)]; });
    csweep<10, 3>(s, 41, 46);
    csweep<9, 5>(s, 42, 45);
    csweep<8, 7>(s, 43, 44);
    // ring d1 + layer1 pool (l10<-l11, l8<-l9, l5<-l7, l1<-l3)
    perm_ph(s,
        [&](int l) {
            return (((l >> 11) & 1) << 10) | (((l >> 9) & 1) << 8) |
                   (((l >> 7) & 1) << 5) | (((l >> 3) & 1) << 1);
        },
        [&](int l) { return g_t1[256 + p4_idx8(l)]; });

    // layer2 d0: w0->l11(U48), w4->l9(U49), w8->l7(U50), w12->l3(U51)
    csweep<11, 3>(s, 48, 51);
    csweep<9, 7>(s, 49, 50);
    // layer2 d1 with ring d0 folded
    csweep_ph<11, 3>(s, 52, 55, [&](int l) { return g_t2[p4_idx4(l)]; });
    csweep<9, 7>(s, 53, 54);
    // ring d1 + layer2 pool (l9<-l11, l3<-l7)
    perm_ph(s,
        [&](int l) {
            return (((l >> 11) & 1) << 9) | (((l >> 7) & 1) << 3);
        },
        [&](int l) { return g_t2[16 + p4_idx4(l)]; });

    // layer3 d0: w0->l11(U56), w8->l7(U57)
    csweep<11, 7>(s, 56, 57);
    // layer3 d1 sweep (U58 on l11, U59 on l7) with t3-d0 phase folded,
    // fused with Z-measurement on l11. No store; t3-d1 + pool3 provably no-op.
    float acc = csweep_meas<11, 7>(s, 58, 59,
        [&](int l) { return g_t3[p4_idx2(l)]; });

    #pragma unroll
    for (int o = 16; o > 0; o >>= 1) acc += __shfl_xor_sync(0xFFFFFFFFu, acc, o);
    if ((tid & 31) == 0) ws[tid >> 5] = acc;
    __syncthreads();
    if (tid == 0) {
        float t = 0.f;
        #pragma unroll
        for (int k = 0; k < 16; k++) t += ws[k];
        atomicAdd(&out[b], t);
    }
}

// ---------------------------------------------------------------------------
extern "C" void kernel_launch(void* const* d_in, const int* in_sizes, int n_in,
                              void* d_out, int out_size) {
    const float* xre = (const float*)d_in[0];
    const float* xim = (const float*)d_in[1];
    const float* p0  = (const float*)d_in[2];
    const float* p1  = (const float*)d_in[3];
    const float* p2  = (const float*)d_in[4];
    const float* p3  = (const float*)d_in[5];
    float* out = (float*)d_out;

    prep_kernel<<<8, 512>>>(p0, p1, p2, p3, out);
    pass1_kernel<<<256, NTP>>>(xre, xim);
    pass2_kernel<<<256, NTP>>>();
    pass3_kernel<<<256, NTP>>>();
    pass4_kernel<<<256, NTP>>>(out);
}